// round 4
// baseline (speedup 1.0000x reference)
#include <cuda_runtime.h>

#define NN  100000
#define NE  1600000
#define IN_DIM  64
#define HID_DIM 48
#define OUT_DIM 32

// ---------------------------------------------------------------------------
// Scratch (device globals — no allocation allowed anywhere)
// ---------------------------------------------------------------------------
__device__ float g_h0  [(size_t)NN * HID_DIM];
__device__ float g_out1[(size_t)NN * HID_DIM];
__device__ float g_h1  [(size_t)NN * OUT_DIM];
__device__ float g_dis [NN];
__device__ float g_norm[NE];
__device__ int   g_src32[NE];
__device__ int   g_dst32[NE];
__device__ int   g_deg [NN];
__device__ int   g_is64;

// ---------------------------------------------------------------------------
// Detect edge_index dtype: int64 values < 2^31 ==> all odd int32 words zero.
// ---------------------------------------------------------------------------
__global__ void k_detect(const int* __restrict__ raw) {
    int all_zero = 1;
    for (int i = 1; i < 128; i += 2)
        if (raw[i] != 0) { all_zero = 0; break; }
    g_is64 = all_zero;
}

// Convert raw edge buffer to int32 src/dst (bounds-clamped defensively).
__global__ void k_convert(const void* __restrict__ raw, int e) {
    int i = blockIdx.x * blockDim.x + threadIdx.x;
    if (i >= e) return;
    int s, d;
    if (g_is64) {
        const long long* p = (const long long*)raw;
        s = (int)p[i];
        d = (int)p[e + i];
    } else {
        const int* p = (const int*)raw;
        s = p[i];
        d = p[e + i];
    }
    // clamp so a wrong dtype guess cannot trap (would fail rel_err, not crash)
    s = min(max(s, 0), NN - 1);
    d = min(max(d, 0), NN - 1);
    g_src32[i] = s;
    g_dst32[i] = d;
}

// ---------------------------------------------------------------------------
// Degree / normalization
// ---------------------------------------------------------------------------
__global__ void k_init_deg(int n) {
    int i = blockIdx.x * blockDim.x + threadIdx.x;
    if (i < n) g_deg[i] = 1;                      // self-loop contributes 1
}

__global__ void k_count(int e) {
    int i = blockIdx.x * blockDim.x + threadIdx.x;
    if (i < e) atomicAdd(&g_deg[g_dst32[i]], 1);
}

__global__ void k_dis(int n) {
    int i = blockIdx.x * blockDim.x + threadIdx.x;
    if (i < n) g_dis[i] = rsqrtf((float)g_deg[i]);
}

__global__ void k_norm(int e) {
    int i = blockIdx.x * blockDim.x + threadIdx.x;
    if (i < e) g_norm[i] = g_dis[g_src32[i]] * g_dis[g_dst32[i]];
}

// ---------------------------------------------------------------------------
// Dense transform: H[n,F] = (relu?)(X[n,K]) @ W[K,F]
// ---------------------------------------------------------------------------
template <int K, int F, bool RELU_IN>
__global__ void k_gemm(const float* __restrict__ X,
                       const float* __restrict__ W,
                       float* __restrict__ H, int n) {
    constexpr int G = F / 4;
    __shared__ float Ws[K * F];
    for (int i = threadIdx.x; i < K * F; i += blockDim.x) Ws[i] = W[i];
    __syncthreads();

    int tid = blockIdx.x * blockDim.x + threadIdx.x;
    int row = tid / G;
    int g   = tid % G;
    if (row >= n) return;

    const float* xr = X + (size_t)row * K;
    float4 acc = make_float4(0.f, 0.f, 0.f, 0.f);
#pragma unroll
    for (int k = 0; k < K; k++) {
        float xv = xr[k];
        if (RELU_IN) xv = fmaxf(xv, 0.f);
        float4 w = *reinterpret_cast<const float4*>(&Ws[k * F + g * 4]);
        acc.x = fmaf(xv, w.x, acc.x);
        acc.y = fmaf(xv, w.y, acc.y);
        acc.z = fmaf(xv, w.z, acc.z);
        acc.w = fmaf(xv, w.w, acc.w);
    }
    *reinterpret_cast<float4*>(&H[(size_t)row * F + g * 4]) = acc;
}

// ---------------------------------------------------------------------------
// Self-loop + bias init: O[i,f] = b[f] + H[i,f] * dis[i]^2
// ---------------------------------------------------------------------------
template <int F>
__global__ void k_self(const float* __restrict__ H,
                       const float* __restrict__ b,
                       float* __restrict__ O, int n) {
    int i = blockIdx.x * blockDim.x + threadIdx.x;
    if (i >= n * F) return;
    int row = i / F;
    int f   = i % F;
    float d = g_dis[row];
    O[i] = b[f] + H[i] * d * d;
}

// ---------------------------------------------------------------------------
// Edge scatter: O[dst] += H[src] * norm.
// One thread per (edge, 4-feature group): float4 gather, 4 scalar red-adds.
// ---------------------------------------------------------------------------
template <int F>
__global__ void k_agg(const float* __restrict__ H,
                      float* __restrict__ O, int e) {
    constexpr int G = F / 4;
    int tid = blockIdx.x * blockDim.x + threadIdx.x;
    int eid = tid / G;
    int g   = tid % G;
    if (eid >= e) return;

    int s = g_src32[eid];
    int d = g_dst32[eid];
    float nm = g_norm[eid];
    float4 v = *reinterpret_cast<const float4*>(&H[(size_t)s * F + g * 4]);
    float* p = &O[(size_t)d * F + g * 4];
    atomicAdd(p + 0, v.x * nm);
    atomicAdd(p + 1, v.y * nm);
    atomicAdd(p + 2, v.z * nm);
    atomicAdd(p + 3, v.w * nm);
}

// ---------------------------------------------------------------------------
// Launch
// ---------------------------------------------------------------------------
static inline int cdiv(long long a, int b) { return (int)((a + b - 1) / b); }

extern "C" void kernel_launch(void* const* d_in, const int* in_sizes, int n_in,
                              void* d_out, int out_size) {
    const float* x   = (const float*)d_in[0];
    const void*  ei  = d_in[1];                  // [2, E], int32 or int64
    const float* W1  = (const float*)d_in[2];
    const float* b1  = (const float*)d_in[3];
    const float* W2  = (const float*)d_in[4];
    const float* b2  = (const float*)d_in[5];
    float*       out = (float*)d_out;

    const int n = in_sizes[0] / IN_DIM;   // 100000
    const int e = in_sizes[1] / 2;        // 1600000

    float *h0, *out1, *h1;
    cudaGetSymbolAddress((void**)&h0,   g_h0);
    cudaGetSymbolAddress((void**)&out1, g_out1);
    cudaGetSymbolAddress((void**)&h1,   g_h1);

    const int T = 256;

    // Edge index conversion + degree + normalization
    k_detect  <<<1, 1>>>((const int*)ei);
    k_convert <<<cdiv(e, T), T>>>(ei, e);
    k_init_deg<<<cdiv(n, T), T>>>(n);
    k_count   <<<cdiv(e, T), T>>>(e);
    k_dis     <<<cdiv(n, T), T>>>(n);
    k_norm    <<<cdiv(e, T), T>>>(e);

    // Layer 1
    k_gemm<IN_DIM, HID_DIM, false><<<cdiv((long long)n * (HID_DIM / 4), T), T>>>(x, W1, h0, n);
    k_self<HID_DIM><<<cdiv((long long)n * HID_DIM, T), T>>>(h0, b1, out1, n);
    k_agg <HID_DIM><<<cdiv((long long)e * (HID_DIM / 4), T), T>>>(h0, out1, e);

    // Layer 2
    k_gemm<HID_DIM, OUT_DIM, true><<<cdiv((long long)n * (OUT_DIM / 4), T), T>>>(out1, W2, h1, n);
    k_self<OUT_DIM><<<cdiv((long long)n * OUT_DIM, T), T>>>(h1, b2, out, n);
    k_agg <OUT_DIM><<<cdiv((long long)e * (OUT_DIM / 4), T), T>>>(h1, out, e);
}

// round 5
// speedup vs baseline: 1.6486x; 1.6486x over previous
#include <cuda_runtime.h>

#define NN  100000
#define NE  1600000
#define IN_DIM  64
#define HID_DIM 48
#define OUT_DIM 32

// ---------------------------------------------------------------------------
// Scratch (device globals — no allocation allowed anywhere)
// ---------------------------------------------------------------------------
__device__ float g_h0  [(size_t)NN * HID_DIM];
__device__ float g_out1[(size_t)NN * HID_DIM];
__device__ float g_h1  [(size_t)NN * OUT_DIM];
__device__ float g_dis [NN];
__device__ float g_norm[NE];
__device__ int   g_src32[NE];
__device__ int   g_dst32[NE];
__device__ int   g_deg [NN];
__device__ int   g_is64;

// ---------------------------------------------------------------------------
// Detect edge_index dtype: int64 values < 2^31 ==> all odd int32 words zero.
// ---------------------------------------------------------------------------
__global__ void k_detect(const int* __restrict__ raw) {
    int all_zero = 1;
    for (int i = 1; i < 128; i += 2)
        if (raw[i] != 0) { all_zero = 0; break; }
    g_is64 = all_zero;
}

__global__ void k_init_deg(int n) {
    int i = blockIdx.x * blockDim.x + threadIdx.x;
    if (i < n) g_deg[i] = 1;                      // self-loop contributes 1
}

// Convert raw edges to int32 src/dst AND count degrees (fused).
__global__ void k_convert(const void* __restrict__ raw, int e) {
    int i = blockIdx.x * blockDim.x + threadIdx.x;
    if (i >= e) return;
    int s, d;
    if (g_is64) {
        const long long* p = (const long long*)raw;
        s = (int)p[i];
        d = (int)p[e + i];
    } else {
        const int* p = (const int*)raw;
        s = p[i];
        d = p[e + i];
    }
    s = min(max(s, 0), NN - 1);                   // defensive clamp (no trap)
    d = min(max(d, 0), NN - 1);
    g_src32[i] = s;
    g_dst32[i] = d;
    atomicAdd(&g_deg[d], 1);
}

__global__ void k_dis(int n) {
    int i = blockIdx.x * blockDim.x + threadIdx.x;
    if (i < n) g_dis[i] = rsqrtf((float)g_deg[i]);
}

__global__ void k_norm(int e) {
    int i = blockIdx.x * blockDim.x + threadIdx.x;
    if (i < e) g_norm[i] = g_dis[g_src32[i]] * g_dis[g_dst32[i]];
}

// ---------------------------------------------------------------------------
// Dense transform + fused self-loop/bias init:
//   H[r,f] = (relu?)(X[r,:]) @ W[:,f]
//   O[r,f] = b[f] + H[r,f] * dis[r]^2
// One thread per (row, 4-feature group). W staged in smem.
// ---------------------------------------------------------------------------
template <int K, int F, bool RELU_IN>
__global__ void k_gemm(const float* __restrict__ X,
                       const float* __restrict__ W,
                       const float* __restrict__ b,
                       float* __restrict__ H,
                       float* __restrict__ O, int n) {
    constexpr int G = F / 4;
    __shared__ float Ws[K * F];
    for (int i = threadIdx.x; i < K * F; i += blockDim.x) Ws[i] = W[i];
    __syncthreads();

    int tid = blockIdx.x * blockDim.x + threadIdx.x;
    int row = tid / G;
    int g   = tid % G;
    if (row >= n) return;

    const float* xr = X + (size_t)row * K;
    float4 acc = make_float4(0.f, 0.f, 0.f, 0.f);
#pragma unroll
    for (int k = 0; k < K; k++) {
        float xv = xr[k];                         // broadcast among G threads
        if (RELU_IN) xv = fmaxf(xv, 0.f);
        float4 w = *reinterpret_cast<const float4*>(&Ws[k * F + g * 4]);
        acc.x = fmaf(xv, w.x, acc.x);
        acc.y = fmaf(xv, w.y, acc.y);
        acc.z = fmaf(xv, w.z, acc.z);
        acc.w = fmaf(xv, w.w, acc.w);
    }
    size_t o = (size_t)row * F + g * 4;
    *reinterpret_cast<float4*>(&H[o]) = acc;

    float ds = g_dis[row];
    float d2 = ds * ds;
    float4 bv = *reinterpret_cast<const float4*>(&b[g * 4]);
    float4 ov = make_float4(bv.x + acc.x * d2, bv.y + acc.y * d2,
                            bv.z + acc.z * d2, bv.w + acc.w * d2);
    *reinterpret_cast<float4*>(&O[o]) = ov;
}

// ---------------------------------------------------------------------------
// Edge scatter: O[dst] += H[src] * norm.
// One thread per (edge, 4-group): float4 gather + ONE red.global.add.v4.f32.
// ---------------------------------------------------------------------------
template <int F>
__global__ void k_agg(const float* __restrict__ H,
                      float* __restrict__ O, int e) {
    constexpr int G = F / 4;
    int tid = blockIdx.x * blockDim.x + threadIdx.x;
    int eid = tid / G;
    int g   = tid % G;
    if (eid >= e) return;

    int s = g_src32[eid];
    int d = g_dst32[eid];
    float nm = g_norm[eid];
    float4 v = *reinterpret_cast<const float4*>(&H[(size_t)s * F + g * 4]);
    float* p = &O[(size_t)d * F + g * 4];
    asm volatile("red.global.add.v4.f32 [%0], {%1,%2,%3,%4};"
                 :: "l"(p),
                    "f"(v.x * nm), "f"(v.y * nm), "f"(v.z * nm), "f"(v.w * nm)
                 : "memory");
}

// ---------------------------------------------------------------------------
// Launch
// ---------------------------------------------------------------------------
static inline int cdiv(long long a, int b) { return (int)((a + b - 1) / b); }

extern "C" void kernel_launch(void* const* d_in, const int* in_sizes, int n_in,
                              void* d_out, int out_size) {
    const float* x   = (const float*)d_in[0];
    const void*  ei  = d_in[1];                  // [2, E], int32 or int64
    const float* W1  = (const float*)d_in[2];
    const float* b1  = (const float*)d_in[3];
    const float* W2  = (const float*)d_in[4];
    const float* b2  = (const float*)d_in[5];
    float*       out = (float*)d_out;

    const int n = in_sizes[0] / IN_DIM;   // 100000
    const int e = in_sizes[1] / 2;        // 1600000

    float *h0, *out1, *h1;
    cudaGetSymbolAddress((void**)&h0,   g_h0);
    cudaGetSymbolAddress((void**)&out1, g_out1);
    cudaGetSymbolAddress((void**)&h1,   g_h1);

    const int T = 256;

    // Edge conversion (+degree count fused) + normalization
    k_detect  <<<1, 1>>>((const int*)ei);
    k_init_deg<<<cdiv(n, T), T>>>(n);
    k_convert <<<cdiv(e, T), T>>>(ei, e);
    k_dis     <<<cdiv(n, T), T>>>(n);
    k_norm    <<<cdiv(e, T), T>>>(e);

    // Layer 1: h0 = x@W1 ; out1 = b1 + self (fused) ; scatter edges
    k_gemm<IN_DIM, HID_DIM, false><<<cdiv((long long)n * (HID_DIM / 4), T), T>>>(x, W1, b1, h0, out1, n);
    k_agg <HID_DIM><<<cdiv((long long)e * (HID_DIM / 4), T), T>>>(h0, out1, e);

    // Layer 2: h1 = relu(out1)@W2 ; out = b2 + self (fused) ; scatter edges
    k_gemm<HID_DIM, OUT_DIM, true><<<cdiv((long long)n * (OUT_DIM / 4), T), T>>>(out1, W2, b2, h1, out, n);
    k_agg <OUT_DIM><<<cdiv((long long)e * (OUT_DIM / 4), T), T>>>(h1, out, e);
}

// round 6
// speedup vs baseline: 1.9862x; 1.2048x over previous
#include <cuda_runtime.h>

#define NN  100000
#define NE  1600000
#define IN_DIM  64
#define HID_DIM 48
#define OUT_DIM 32

#define SCAN_B 512                      // scan block size
#define SCAN_NBLK ((NN + SCAN_B - 1) / SCAN_B)

// ---------------------------------------------------------------------------
// Scratch (device globals)
// ---------------------------------------------------------------------------
__device__ float g_h0  [(size_t)NN * HID_DIM];   // x @ W1
__device__ float g_out1[(size_t)NN * HID_DIM];   // layer-1 output (relu input)
__device__ float g_h1  [(size_t)NN * OUT_DIM];   // relu(out1) @ W2
__device__ float g_dis [NN];                     // deg^{-1/2}
__device__ int2  g_edge[NE];                     // (src, dst) parsed
__device__ int2  g_erec[NE];                     // CSR records: (src, bitcast norm)
__device__ int   g_cnt [NN];                     // in-degree (excl. self-loop)
__device__ int   g_fill[NN];                     // fill cursors
__device__ int   g_rowptr[NN + 1];
__device__ int   g_part[NN];                     // scan partials
__device__ int   g_bsum[SCAN_NBLK];              // scan block sums
__device__ int   g_is64;

// ---------------------------------------------------------------------------
// Edge dtype detect: int64 values < 2^31 ==> all odd int32 words zero.
// ---------------------------------------------------------------------------
__global__ void k_detect(const int* __restrict__ raw) {
    int all_zero = 1;
    for (int i = 1; i < 128; i += 2)
        if (raw[i] != 0) { all_zero = 0; break; }
    g_is64 = all_zero;
}

__global__ void k_zero(int n) {
    int i = blockIdx.x * blockDim.x + threadIdx.x;
    if (i < n) { g_cnt[i] = 0; g_fill[i] = 0; }
}

// Parse raw edges -> int2, count in-degrees.
__global__ void k_convert(const void* __restrict__ raw, int e) {
    int i = blockIdx.x * blockDim.x + threadIdx.x;
    if (i >= e) return;
    int s, d;
    if (g_is64) {
        const long long* p = (const long long*)raw;
        s = (int)p[i];
        d = (int)p[e + i];
    } else {
        const int* p = (const int*)raw;
        s = p[i];
        d = p[e + i];
    }
    s = min(max(s, 0), NN - 1);
    d = min(max(d, 0), NN - 1);
    g_edge[i] = make_int2(s, d);
    atomicAdd(&g_cnt[d], 1);
}

__global__ void k_dis(int n) {
    int i = blockIdx.x * blockDim.x + threadIdx.x;
    if (i < n) g_dis[i] = rsqrtf((float)(g_cnt[i] + 1));   // +1 self-loop
}

// ---------------------------------------------------------------------------
// Exclusive scan of g_cnt -> g_rowptr  (3 kernels)
// ---------------------------------------------------------------------------
__global__ void k_scan1(int n) {
    __shared__ int sh[SCAN_B];
    int i = blockIdx.x * SCAN_B + threadIdx.x;
    int v = (i < n) ? g_cnt[i] : 0;
    sh[threadIdx.x] = v;
    __syncthreads();
#pragma unroll
    for (int off = 1; off < SCAN_B; off <<= 1) {
        int t = (threadIdx.x >= off) ? sh[threadIdx.x - off] : 0;
        __syncthreads();
        sh[threadIdx.x] += t;
        __syncthreads();
    }
    if (i < n) g_part[i] = sh[threadIdx.x] - v;            // exclusive
    if (threadIdx.x == SCAN_B - 1) g_bsum[blockIdx.x] = sh[SCAN_B - 1];
}

__global__ void k_scan2() {                                 // one block
    __shared__ int sh[SCAN_NBLK];
    int t = threadIdx.x;
    for (int i = t; i < SCAN_NBLK; i += blockDim.x) sh[i] = g_bsum[i];
    __syncthreads();
    if (t == 0) {                                           // serial: 196 elems
        int run = 0;
        for (int i = 0; i < SCAN_NBLK; i++) { int v = sh[i]; sh[i] = run; run += v; }
    }
    __syncthreads();
    for (int i = t; i < SCAN_NBLK; i += blockDim.x) g_bsum[i] = sh[i];
}

__global__ void k_scan3(int n, int e) {
    int i = blockIdx.x * SCAN_B + threadIdx.x;
    if (i < n) g_rowptr[i] = g_part[i] + g_bsum[blockIdx.x];
    if (i == 0) g_rowptr[n] = e;
}

// ---------------------------------------------------------------------------
// CSR fill: slot in dst's list, record = (src, norm)
// ---------------------------------------------------------------------------
__global__ void k_fill(int e) {
    int i = blockIdx.x * blockDim.x + threadIdx.x;
    if (i >= e) return;
    int2 ed = g_edge[i];
    float nm = g_dis[ed.x] * g_dis[ed.y];
    int pos = g_rowptr[ed.y] + atomicAdd(&g_fill[ed.y], 1);
    g_erec[pos] = make_int2(ed.x, __float_as_int(nm));
}

// ---------------------------------------------------------------------------
// Dense transform: H[n,F] = (relu?)(X[n,K]) @ W[K,F]   (H only)
// ---------------------------------------------------------------------------
template <int K, int F, bool RELU_IN>
__global__ void k_gemm(const float* __restrict__ X,
                       const float* __restrict__ W,
                       float* __restrict__ H, int n) {
    constexpr int G = F / 4;
    __shared__ float Ws[K * F];
    for (int i = threadIdx.x; i < K * F; i += blockDim.x) Ws[i] = W[i];
    __syncthreads();

    int tid = blockIdx.x * blockDim.x + threadIdx.x;
    int row = tid / G;
    int g   = tid % G;
    if (row >= n) return;

    const float* xr = X + (size_t)row * K;
    float4 acc = make_float4(0.f, 0.f, 0.f, 0.f);
#pragma unroll
    for (int k = 0; k < K; k++) {
        float xv = xr[k];
        if (RELU_IN) xv = fmaxf(xv, 0.f);
        float4 w = *reinterpret_cast<const float4*>(&Ws[k * F + g * 4]);
        acc.x = fmaf(xv, w.x, acc.x);
        acc.y = fmaf(xv, w.y, acc.y);
        acc.z = fmaf(xv, w.z, acc.z);
        acc.w = fmaf(xv, w.w, acc.w);
    }
    *reinterpret_cast<float4*>(&H[(size_t)row * F + g * 4]) = acc;
}

// ---------------------------------------------------------------------------
// CSR gather-aggregate (no atomics):
//   O[v,f] = b[f] + H[v,f]*dis[v]^2 + sum_{(s,nm) in list(v)} H[s,f]*nm
// Thread = (node, 4-feature group).
// ---------------------------------------------------------------------------
template <int F>
__global__ void k_aggcsr(const float* __restrict__ H,
                         const float* __restrict__ b,
                         float* __restrict__ O, int n) {
    constexpr int G = F / 4;
    int tid = blockIdx.x * blockDim.x + threadIdx.x;
    int node = tid / G;
    int g    = tid % G;
    if (node >= n) return;

    size_t o = (size_t)node * F + g * 4;
    float ds = g_dis[node];
    float d2 = ds * ds;
    float4 h  = *reinterpret_cast<const float4*>(&H[o]);
    float4 bv = *reinterpret_cast<const float4*>(&b[g * 4]);
    float4 acc = make_float4(bv.x + h.x * d2, bv.y + h.y * d2,
                             bv.z + h.z * d2, bv.w + h.w * d2);

    int beg = g_rowptr[node];
    int end = g_rowptr[node + 1];
#pragma unroll 2
    for (int j = beg; j < end; j++) {
        int2 r = g_erec[j];                         // broadcast across G threads
        float nm = __int_as_float(r.y);
        float4 v = *reinterpret_cast<const float4*>(&H[(size_t)r.x * F + g * 4]);
        acc.x = fmaf(v.x, nm, acc.x);
        acc.y = fmaf(v.y, nm, acc.y);
        acc.z = fmaf(v.z, nm, acc.z);
        acc.w = fmaf(v.w, nm, acc.w);
    }
    *reinterpret_cast<float4*>(&O[o]) = acc;
}

// ---------------------------------------------------------------------------
// Launch
// ---------------------------------------------------------------------------
static inline int cdiv(long long a, int b) { return (int)((a + b - 1) / b); }

extern "C" void kernel_launch(void* const* d_in, const int* in_sizes, int n_in,
                              void* d_out, int out_size) {
    const float* x   = (const float*)d_in[0];
    const void*  ei  = d_in[1];
    const float* W1  = (const float*)d_in[2];
    const float* b1  = (const float*)d_in[3];
    const float* W2  = (const float*)d_in[4];
    const float* b2  = (const float*)d_in[5];
    float*       out = (float*)d_out;

    const int n = in_sizes[0] / IN_DIM;   // 100000
    const int e = in_sizes[1] / 2;        // 1600000

    float *h0, *out1, *h1;
    cudaGetSymbolAddress((void**)&h0,   g_h0);
    cudaGetSymbolAddress((void**)&out1, g_out1);
    cudaGetSymbolAddress((void**)&h1,   g_h1);

    const int T = 256;

    // CSR build
    k_detect <<<1, 1>>>((const int*)ei);
    k_zero   <<<cdiv(n, T), T>>>(n);
    k_convert<<<cdiv(e, T), T>>>(ei, e);
    k_dis    <<<cdiv(n, T), T>>>(n);
    k_scan1  <<<SCAN_NBLK, SCAN_B>>>(n);
    k_scan2  <<<1, 256>>>();
    k_scan3  <<<SCAN_NBLK, SCAN_B>>>(n, e);
    k_fill   <<<cdiv(e, T), T>>>(e);

    // Layer 1
    k_gemm<IN_DIM, HID_DIM, false><<<cdiv((long long)n * (HID_DIM / 4), T), T>>>(x, W1, h0, n);
    k_aggcsr<HID_DIM><<<cdiv((long long)n * (HID_DIM / 4), T), T>>>(h0, b1, out1, n);

    // Layer 2
    k_gemm<HID_DIM, OUT_DIM, true><<<cdiv((long long)n * (OUT_DIM / 4), T), T>>>(out1, W2, h1, n);
    k_aggcsr<OUT_DIM><<<cdiv((long long)n * (OUT_DIM / 4), T), T>>>(h1, b2, out, n);
}